// round 1
// baseline (speedup 1.0000x reference)
#include <cuda_runtime.h>

#define DIN 784
#define H 32
#define KC 56
#define NCHUNK 14   /* 784 / 56 */
#define TM 128      /* rows per block */
#define NTH 128
#define SXS 57      /* x smem row stride (conflict-free reads) */
#define SHS 36      /* h smem row stride (16B-aligned rows) */

typedef unsigned long long ull;

__device__ float2 g_U[256];   // U[j][b] row-major, complex

__device__ __forceinline__ void fma2(ull &d, ull a, ull b){
    asm("fma.rn.f32x2 %0, %1, %2, %0;" : "+l"(d) : "l"(a), "l"(b));
}
__device__ __forceinline__ ull dup2(float v){
    ull r; asm("mov.b64 %0, {%1, %1};" : "=l"(r) : "f"(v)); return r;
}
__device__ __forceinline__ float2 unpack2(ull v){
    float2 r; asm("mov.b64 {%0, %1}, %2;" : "=f"(r.x), "=f"(r.y) : "l"(v)); return r;
}
__device__ __forceinline__ float2 cmul(float2 a, float2 b){
    return make_float2(a.x*b.x - a.y*b.y, a.x*b.y + a.y*b.x);
}

// ---------------------------------------------------------------------------
// Kernel A: build the 16x16 complex unitary from shared_w (2 layers) +
// task_w (1 layer). Runs once, 1 block, trivially cheap.
// ---------------------------------------------------------------------------
__global__ void build_U_kernel(const float* __restrict__ shared_w,
                               const float* __restrict__ task_w){
    __shared__ float2 U[16][16];
    int tid = threadIdx.x;
    for (int i = tid; i < 256; i += NTH)
        U[i>>4][i&15] = make_float2((i>>4)==(i&15) ? 1.f : 0.f, 0.f);
    __syncthreads();

    for (int l = 0; l < 3; l++){
        const float* wp = (l < 2) ? (shared_w + l*12) : task_w;
        // single-qubit rotations, wires 0..3 (applied left: U <- G @ U)
        for (int wire = 0; wire < 4; wire++){
            float phi = wp[wire*3+0], th = wp[wire*3+1], om = wp[wire*3+2];
            float ch = cosf(0.5f*th), shn = sinf(0.5f*th);
            float a = 0.5f*(phi+om), d = 0.5f*(phi-om);
            float sa, ca, sd, cd;
            sincosf(a, &sa, &ca); sincosf(d, &sd, &cd);
            float2 m00 = make_float2( ca*ch, -sa*ch);
            float2 m01 = make_float2(-cd*shn, -sd*shn);
            float2 m10 = make_float2( cd*shn, -sd*shn);
            float2 m11 = make_float2( ca*ch,  sa*ch);
            int bp = 3 - wire;
            {   // 8 row-pairs x 16 cols = 128 tasks, one per thread
                int p = tid >> 4, col = tid & 15;
                int r0 = ((p >> bp) << (bp+1)) | (p & ((1<<bp)-1));
                int r1 = r0 | (1 << bp);
                float2 u0 = U[r0][col], u1 = U[r1][col];
                float2 t0 = cmul(m00,u0), t1 = cmul(m01,u1);
                float2 t2 = cmul(m10,u0), t3 = cmul(m11,u1);
                float2 n0 = make_float2(t0.x+t1.x, t0.y+t1.y);
                float2 n1 = make_float2(t2.x+t3.x, t2.y+t3.y);
                U[r0][col] = n0; U[r1][col] = n1;
            }
            __syncthreads();
        }
        // CNOT ring, applied sequentially (they don't commute)
        int r = (l == 1) ? 2 : 1;
        for (int i = 0; i < 4; i++){
            int c = i, t = (i + r) & 3;
            int pc = 3 - c, pt = 3 - t;
            if (tid < 64){
                int idx = tid >> 4, col = tid & 15;
                int rem0 = -1, rem1 = -1;
                for (int bit = 3; bit >= 0; bit--)
                    if (bit != pc && bit != pt){ if (rem0 < 0) rem0 = bit; else rem1 = bit; }
                int b  = (1 << pc) | (((idx>>1)&1) << rem0) | ((idx&1) << rem1);
                int b2 = b | (1 << pt);
                float2 tmp = U[b][col]; U[b][col] = U[b2][col]; U[b2][col] = tmp;
            }
            __syncthreads();
        }
    }
    for (int i = tid; i < 256; i += NTH) g_U[i] = U[i>>4][i&15];
}

// ---------------------------------------------------------------------------
// Kernel B: fused GEMM(65536x784x32, fp32 via packed f32x2 FMA) + bias/ReLU +
// LayerNorm + 32->4 GEMM + tanh + product-state + 16x16 complex matvec +
// sign-sums + 4->2 head.
// Block: 128 threads, 128 rows. Thread = 4 rows x 8 cols (col-paired FFMA2).
// ---------------------------------------------------------------------------
__global__ void __launch_bounds__(NTH) fused_kernel(
    const float* __restrict__ x,   const float* __restrict__ w1,
    const float* __restrict__ b1,  const float* __restrict__ lng,
    const float* __restrict__ lnb, const float* __restrict__ w2,
    const float* __restrict__ b2,  const float* __restrict__ pw,
    const float* __restrict__ pb,  float2* __restrict__ out)
{
    __shared__ float  s_pool[TM*SXS];   // x tile; reused as h tile (TM*SHS) after GEMM
    __shared__ float  s_w[KC*H];
    __shared__ float2 s_U[256];
    __shared__ float  s_b1[H], s_g[H], s_b[H], s_w2[H*4], s_b2[4], s_pw[8], s_pb[2];

    const int tid = threadIdx.x;
    const int tc  = tid & 3;        // col group: cols tc*8 .. tc*8+7
    const int tr  = tid >> 2;       // row group: rows tr*4 .. tr*4+3
    const int row0 = blockIdx.x * TM;

    // stage tiny params + U (covered by the first __syncthreads below)
    ((float4*)s_U)[tid] = ((const float4*)g_U)[tid];   // 128 * 16B = 2KB
    if (tid < H)  { s_b1[tid] = b1[tid]; s_g[tid] = lng[tid]; s_b[tid] = lnb[tid]; }
    if (tid < H*4)  s_w2[tid] = w2[tid];
    if (tid < 4)    s_b2[tid] = b2[tid];
    if (tid < 8)    s_pw[tid] = pw[tid];
    if (tid < 2)    s_pb[tid] = pb[tid];

    ull acc[4][4];
    #pragma unroll
    for (int j = 0; j < 4; j++)
        #pragma unroll
        for (int cp = 0; cp < 4; cp++) acc[j][cp] = 0ull;

    const int rbase = tr * 4;

    for (int ch = 0; ch < NCHUNK; ch++){
        __syncthreads();   // prior-iter reads done before overwriting s_pool
        const int kc0 = ch * KC;
        // stage x tile: 128 rows x 56 floats = 1792 float4, coalesced
        #pragma unroll
        for (int it = 0; it < 14; it++){
            int i   = it*NTH + tid;
            int row = i / 14, seg = i % 14;
            float4 v = *(const float4*)&x[(size_t)(row0+row)*DIN + kc0 + seg*4];
            float* dst = &s_pool[row*SXS + seg*4];
            dst[0]=v.x; dst[1]=v.y; dst[2]=v.z; dst[3]=v.w;
        }
        // stage w1 chunk: contiguous 56*32 floats = 448 float4
        const float4* wsrc = (const float4*)&w1[(size_t)kc0 * H];
        #pragma unroll
        for (int it = 0; it < 4; it++){
            int i = it*NTH + tid;
            if (i < 448) ((float4*)s_w)[i] = wsrc[i];
        }
        __syncthreads();

        const float* xr0 = &s_pool[(rbase+0)*SXS];
        const float* xr1 = &s_pool[(rbase+1)*SXS];
        const float* xr2 = &s_pool[(rbase+2)*SXS];
        const float* xr3 = &s_pool[(rbase+3)*SXS];

        #pragma unroll 8
        for (int k = 0; k < KC; k++){
            ull x0 = dup2(xr0[k]);
            ull x1 = dup2(xr1[k]);
            ull x2 = dup2(xr2[k]);
            ull x3 = dup2(xr3[k]);
            const ull* wk = (const ull*)&s_w[k*H + tc*8];   // 16B aligned
            ull w0 = wk[0], wv1 = wk[1], wv2 = wk[2], wv3 = wk[3];
            fma2(acc[0][0], x0, w0); fma2(acc[0][1], x0, wv1);
            fma2(acc[0][2], x0, wv2); fma2(acc[0][3], x0, wv3);
            fma2(acc[1][0], x1, w0); fma2(acc[1][1], x1, wv1);
            fma2(acc[1][2], x1, wv2); fma2(acc[1][3], x1, wv3);
            fma2(acc[2][0], x2, w0); fma2(acc[2][1], x2, wv1);
            fma2(acc[2][2], x2, wv2); fma2(acc[2][3], x2, wv3);
            fma2(acc[3][0], x3, w0); fma2(acc[3][1], x3, wv1);
            fma2(acc[3][2], x3, wv2); fma2(acc[3][3], x3, wv3);
        }
    }
    __syncthreads();   // all sx reads done; s_pool now becomes the h tile

    // bias + ReLU, scatter into h tile
    #pragma unroll
    for (int j = 0; j < 4; j++){
        int row = rbase + j;
        #pragma unroll
        for (int cp = 0; cp < 4; cp++){
            float2 p = unpack2(acc[j][cp]);
            int col = tc*8 + cp*2;
            float v0 = p.x + s_b1[col];     v0 = v0 > 0.f ? v0 : 0.f;
            float v1 = p.y + s_b1[col+1];   v1 = v1 > 0.f ? v1 : 0.f;
            s_pool[row*SHS + col]     = v0;
            s_pool[row*SHS + col + 1] = v1;
        }
    }
    __syncthreads();

    // per-row epilogue: one thread = one row
    {
        float h[32];
        const float4* hr = (const float4*)&s_pool[tid*SHS];   // 36*4B rows: 16B aligned
        #pragma unroll
        for (int q = 0; q < 8; q++){
            float4 v = hr[q];
            h[q*4]=v.x; h[q*4+1]=v.y; h[q*4+2]=v.z; h[q*4+3]=v.w;
        }
        float mu = 0.f;
        #pragma unroll
        for (int c = 0; c < 32; c++) mu += h[c];
        mu *= (1.f/32.f);
        float var = 0.f;
        #pragma unroll
        for (int c = 0; c < 32; c++){ float d = h[c]-mu; var += d*d; }
        var *= (1.f/32.f);
        float inv = rsqrtf(var + 1e-5f);

        float z0 = s_b2[0], z1 = s_b2[1], z2 = s_b2[2], z3 = s_b2[3];
        #pragma unroll
        for (int c = 0; c < 32; c++){
            float hn = (h[c]-mu)*inv*s_g[c] + s_b[c];
            z0 += hn * s_w2[c*4+0];
            z1 += hn * s_w2[c*4+1];
            z2 += hn * s_w2[c*4+2];
            z3 += hn * s_w2[c*4+3];
        }
        float cs[4], sn[4];
        float zz;
        zz = tanhf(z0) * 1.5707963267948966f; sincosf(zz, &sn[0], &cs[0]);
        zz = tanhf(z1) * 1.5707963267948966f; sincosf(zz, &sn[1], &cs[1]);
        zz = tanhf(z2) * 1.5707963267948966f; sincosf(zz, &sn[2], &cs[2]);
        zz = tanhf(z3) * 1.5707963267948966f; sincosf(zz, &sn[3], &cs[3]);

        // product state (real): psi[b] = prod_q (bit ? sin : cos), q0 = MSB
        float t01[4], t23[4], psi[16];
        t01[0]=cs[0]*cs[1]; t01[1]=cs[0]*sn[1]; t01[2]=sn[0]*cs[1]; t01[3]=sn[0]*sn[1];
        t23[0]=cs[2]*cs[3]; t23[1]=cs[2]*sn[3]; t23[2]=sn[2]*cs[3]; t23[3]=sn[2]*sn[3];
        #pragma unroll
        for (int bb = 0; bb < 16; bb++) psi[bb] = t01[bb>>2]*t23[bb&3];

        // psi_out[j] = sum_b psi[b] * U[j][b]; probs -> signed sums
        float e0=0.f, e1=0.f, e2=0.f, e3=0.f;
        #pragma unroll 4
        for (int j = 0; j < 16; j++){
            float re = 0.f, im = 0.f;
            #pragma unroll
            for (int bb = 0; bb < 16; bb++){
                float2 u = s_U[j*16 + bb];
                re += psi[bb]*u.x;
                im += psi[bb]*u.y;
            }
            float p = re*re + im*im;
            e0 += (j & 8) ? -p : p;
            e1 += (j & 4) ? -p : p;
            e2 += (j & 2) ? -p : p;
            e3 += (j & 1) ? -p : p;
        }
        float o0 = s_pb[0] + e0*s_pw[0] + e1*s_pw[2] + e2*s_pw[4] + e3*s_pw[6];
        float o1 = s_pb[1] + e0*s_pw[1] + e1*s_pw[3] + e2*s_pw[5] + e3*s_pw[7];
        out[row0 + tid] = make_float2(o0, o1);
    }
}

// ---------------------------------------------------------------------------
extern "C" void kernel_launch(void* const* d_in, const int* in_sizes, int n_in,
                              void* d_out, int out_size)
{
    const float* x   = (const float*)d_in[0];
    const float* w1  = (const float*)d_in[1];
    const float* b1  = (const float*)d_in[2];
    const float* lng = (const float*)d_in[3];
    const float* lnb = (const float*)d_in[4];
    const float* w2  = (const float*)d_in[5];
    const float* b2  = (const float*)d_in[6];
    const float* sw  = (const float*)d_in[7];
    const float* tw  = (const float*)d_in[8];
    const float* pw  = (const float*)d_in[9];
    const float* pb  = (const float*)d_in[10];
    (void)n_in; (void)out_size;

    int rows = in_sizes[0] / DIN;

    build_U_kernel<<<1, NTH>>>(sw, tw);
    fused_kernel<<<rows / TM, NTH>>>(x, w1, b1, lng, lnb, w2, b2, pw, pb,
                                     (float2*)d_out);
}